// round 1
// baseline (speedup 1.0000x reference)
#include <cuda_runtime.h>

#define B_ 16
#define N_ 1024
#define D_ 64
#define C_ 64
#define K_ 20
#define EPS_ 0.001f

// scratch (no cudaMalloc allowed)
__device__ int   g_nn_idx[B_ * N_ * K_];
__device__ float g_f0[B_ * N_];

// ---------------------------------------------------------------------------
// Kernel 0: densify f0 = feats[:,:,0] so topk reads are coalesced
// ---------------------------------------------------------------------------
__global__ void extract_f0_kernel(const float* __restrict__ feats) {
    int i = blockIdx.x * blockDim.x + threadIdx.x;
    if (i < B_ * N_) g_f0[i] = feats[(size_t)i * D_];
}

// ---------------------------------------------------------------------------
// Kernel 1: exact top-20 smallest of a[j] = adj[b,n,j]*|f0[b,j]-f0[b,n]| per row.
// Key = (float_bits(a) << 32) | j  (a >= 0 so uint compare == float compare;
// embedded index gives lowest-index tie-break, matching jax.lax.top_k).
// ---------------------------------------------------------------------------
__global__ void topk_kernel(const float* __restrict__ adj) {
    const int row  = blockIdx.x;            // b*N + n
    const int b    = row >> 10;
    const int tid  = threadIdx.x;           // 256 threads
    const int lane = tid & 31;
    const int wid  = tid >> 5;              // 8 warps

    const float  f0n  = g_f0[row];
    const float* arow = adj + (size_t)row * N_;
    const float* f0b  = g_f0 + b * N_;

    unsigned long long key[4];
#pragma unroll
    for (int t = 0; t < 4; t++) {
        int j = tid + t * 256;
        float a = arow[j] * fabsf(f0b[j] - f0n);
        key[t] = ((unsigned long long)__float_as_uint(a) << 32) | (unsigned)j;
    }
    // sort 4 ascending (network)
#define CSWP(x, y) { unsigned long long lo = (x) < (y) ? (x) : (y); \
                     unsigned long long hi = (x) < (y) ? (y) : (x); (x) = lo; (y) = hi; }
    CSWP(key[0], key[1]); CSWP(key[2], key[3]);
    CSWP(key[0], key[2]); CSWP(key[1], key[3]);
    CSWP(key[1], key[2]);
#undef CSWP

    __shared__ unsigned long long cand[8][K_];

    // per-warp top-20 of its 128 elements (global top-20 is a subset of the union)
#pragma unroll 1
    for (int i = 0; i < K_; i++) {
        unsigned long long mykey = key[0];
        unsigned long long m = mykey;
#pragma unroll
        for (int off = 16; off; off >>= 1) {
            unsigned long long o = __shfl_down_sync(0xffffffffu, m, off);
            m = (o < m) ? o : m;
        }
        m = __shfl_sync(0xffffffffu, m, 0);
        if (lane == 0) cand[wid][i] = m;
        if (mykey == m) {   // keys unique (index embedded) -> exactly one lane
            key[0] = key[1]; key[1] = key[2]; key[2] = key[3];
            key[3] = ~0ULL;
        }
    }
    __syncthreads();

    // 8-way merge of sorted candidate lists, done by warp 0 (lanes 0..7 own lists)
    if (wid == 0) {
        int q = 0;
        const int out_base = row * K_;
#pragma unroll 1
        for (int i = 0; i < K_; i++) {
            unsigned long long mykey = (lane < 8) ? cand[lane][q] : ~0ULL;
            unsigned long long m = mykey;
#pragma unroll
            for (int off = 4; off; off >>= 1) {
                unsigned long long o = __shfl_down_sync(0xffffffffu, m, off);
                m = (o < m) ? o : m;
            }
            m = __shfl_sync(0xffffffffu, m, 0);
            if (lane == 0) g_nn_idx[out_base + i] = (int)(unsigned)(m & 0xFFFFFFFFu);
            if (mykey == m && lane < 8) q++;
        }
    }
}

// ---------------------------------------------------------------------------
// Kernel 2: fused gather + (edge@w1+BN+relu) + (@w2+BN+relu) + mean over k.
// BN folded into weights. edge@w1 split: center part computed once per node,
// diff part per neighbor. Thread c owns output channel c; weight columns for
// the per-k matvecs live in registers; activations broadcast from smem.
// 128 threads = 2 nodes in parallel (grp = tid>>6); 8 sequential pairs/block.
// ---------------------------------------------------------------------------
__global__ void __launch_bounds__(128, 2) edgeconv_kernel(
    const float* __restrict__ feats,
    const float* __restrict__ w1,  const float* __restrict__ b1,
    const float* __restrict__ g1,  const float* __restrict__ be1,
    const float* __restrict__ mu1, const float* __restrict__ v1,
    const float* __restrict__ w2,  const float* __restrict__ b2,
    const float* __restrict__ g2,  const float* __restrict__ be2,
    const float* __restrict__ mu2, const float* __restrict__ v2,
    float* __restrict__ out)
{
    __shared__ __align__(16) float w1c_s[D_ * C_];   // folded w1[0:64,:], [d][c]
    __shared__ __align__(16) float cf[2][C_];
    __shared__ __align__(16) float dbuf[2][C_];
    __shared__ __align__(16) float hbuf[2][C_];

    const int tid = threadIdx.x;
    const int c   = tid & (C_ - 1);
    const int grp = tid >> 6;

    const float s1c = g1[c] * rsqrtf(v1[c] + EPS_);
    const float b1f = (b1[c] - mu1[c]) * s1c + be1[c];
    const float s2c = g2[c] * rsqrtf(v2[c] + EPS_);
    const float b2f = (b2[c] - mu2[c]) * s2c + be2[c];

    float w1d_col[D_];   // folded w1[64+d][c]
    float w2_col[C_];    // folded w2[e][c]
#pragma unroll
    for (int d = 0; d < D_; d++) w1d_col[d] = w1[(D_ + d) * C_ + c] * s1c;
#pragma unroll
    for (int e = 0; e < C_; e++) w2_col[e]  = w2[e * C_ + c] * s2c;
    if (grp == 0) {
#pragma unroll
        for (int d = 0; d < D_; d++) w1c_s[d * C_ + c] = w1[d * C_ + c] * s1c;
    }
    __syncthreads();

#pragma unroll 1
    for (int i = 0; i < 8; i++) {
        const int node = blockIdx.x * 16 + i * 2 + grp;   // b*N + n
        const float fc = feats[node * D_ + c];
        cf[grp][c] = fc;
        __syncthreads();

        // center contribution to layer-1 pre-activation (once per node)
        float cp0 = b1f, cp1 = 0.f, cp2 = 0.f, cp3 = 0.f;
#pragma unroll
        for (int d = 0; d < D_; d += 4) {
            float4 dv = *(const float4*)&cf[grp][d];
            cp0 += dv.x * w1c_s[(d + 0) * C_ + c];
            cp1 += dv.y * w1c_s[(d + 1) * C_ + c];
            cp2 += dv.z * w1c_s[(d + 2) * C_ + c];
            cp3 += dv.w * w1c_s[(d + 3) * C_ + c];
        }
        const float cpart = (cp0 + cp1) + (cp2 + cp3);

        float acc = 0.f;
        const int* nn    = g_nn_idx + node * K_;
        const int  bbase = (node >> 10) << 10;   // b*N

#pragma unroll 1
        for (int k = 0; k < K_; k++) {
            const int nb = nn[k];
            dbuf[grp][c] = feats[(bbase + nb) * D_ + c] - fc;
            __syncthreads();

            float h0 = cpart, h1 = 0.f, h2 = 0.f, h3 = 0.f;
#pragma unroll
            for (int d = 0; d < D_; d += 4) {
                float4 dv = *(const float4*)&dbuf[grp][d];
                h0 += dv.x * w1d_col[d + 0];
                h1 += dv.y * w1d_col[d + 1];
                h2 += dv.z * w1d_col[d + 2];
                h3 += dv.w * w1d_col[d + 3];
            }
            hbuf[grp][c] = fmaxf((h0 + h1) + (h2 + h3), 0.f);
            __syncthreads();

            float y0 = b2f, y1 = 0.f, y2 = 0.f, y3 = 0.f;
#pragma unroll
            for (int e = 0; e < C_; e += 4) {
                float4 hv = *(const float4*)&hbuf[grp][e];
                y0 += hv.x * w2_col[e + 0];
                y1 += hv.y * w2_col[e + 1];
                y2 += hv.z * w2_col[e + 2];
                y3 += hv.w * w2_col[e + 3];
            }
            acc += fmaxf((y0 + y1) + (y2 + y3), 0.f);
        }
        out[node * C_ + c] = acc * (1.0f / K_);
        // next iteration's cf write is ordered by the __syncthreads after it
    }
}

// ---------------------------------------------------------------------------
extern "C" void kernel_launch(void* const* d_in, const int* in_sizes, int n_in,
                              void* d_out, int out_size)
{
    const float* feats = (const float*)d_in[0];
    const float* adj   = (const float*)d_in[1];
    const float* w1    = (const float*)d_in[2];
    const float* b1    = (const float*)d_in[3];
    const float* g1    = (const float*)d_in[4];
    const float* be1   = (const float*)d_in[5];
    const float* mu1   = (const float*)d_in[6];
    const float* v1    = (const float*)d_in[7];
    const float* w2    = (const float*)d_in[8];
    const float* b2    = (const float*)d_in[9];
    const float* g2    = (const float*)d_in[10];
    const float* be2   = (const float*)d_in[11];
    const float* mu2   = (const float*)d_in[12];
    const float* v2    = (const float*)d_in[13];
    float* out = (float*)d_out;

    extract_f0_kernel<<<(B_ * N_ + 1023) / 1024, 1024>>>(feats);
    topk_kernel<<<B_ * N_, 256>>>(adj);
    edgeconv_kernel<<<(B_ * N_) / 16, 128>>>(feats, w1, b1, g1, be1, mu1, v1,
                                             w2, b2, g2, be2, mu2, v2, out);
}

// round 2
// speedup vs baseline: 1.2948x; 1.2948x over previous
#include <cuda_runtime.h>

#define B_ 16
#define N_ 1024
#define D_ 64
#define C_ 64
#define K_ 20
#define EPS_ 0.001f

// scratch (no cudaMalloc allowed)
__device__ int   g_nn_idx[B_ * N_ * K_];
__device__ float g_f0[B_ * N_];

// ---------------------------------------------------------------------------
// Kernel 0: densify f0 = feats[:,:,0] so topk reads are coalesced
// ---------------------------------------------------------------------------
__global__ void extract_f0_kernel(const float* __restrict__ feats) {
    int i = blockIdx.x * blockDim.x + threadIdx.x;
    if (i < B_ * N_) g_f0[i] = feats[(size_t)i * D_];
}

// ---------------------------------------------------------------------------
// Kernel 1: exact top-20 smallest of a[j] = adj[b,n,j]*|f0[b,j]-f0[b,n]| per row.
// Key = (float_bits(a) << 32) | j  (a >= 0 so uint compare == float compare;
// embedded index gives lowest-index tie-break, matching jax.lax.top_k).
// ---------------------------------------------------------------------------
__global__ void topk_kernel(const float* __restrict__ adj) {
    const int row  = blockIdx.x;            // b*N + n
    const int b    = row >> 10;
    const int tid  = threadIdx.x;           // 256 threads
    const int lane = tid & 31;
    const int wid  = tid >> 5;              // 8 warps

    const float  f0n  = g_f0[row];
    const float* arow = adj + (size_t)row * N_;
    const float* f0b  = g_f0 + b * N_;

    unsigned long long key[4];
#pragma unroll
    for (int t = 0; t < 4; t++) {
        int j = tid + t * 256;
        float a = arow[j] * fabsf(f0b[j] - f0n);
        key[t] = ((unsigned long long)__float_as_uint(a) << 32) | (unsigned)j;
    }
    // sort 4 ascending (network)
#define CSWP(x, y) { unsigned long long lo = (x) < (y) ? (x) : (y); \
                     unsigned long long hi = (x) < (y) ? (y) : (x); (x) = lo; (y) = hi; }
    CSWP(key[0], key[1]); CSWP(key[2], key[3]);
    CSWP(key[0], key[2]); CSWP(key[1], key[3]);
    CSWP(key[1], key[2]);
#undef CSWP

    __shared__ unsigned long long cand[8][K_];

    // per-warp top-20 of its 128 elements (global top-20 is a subset of the union)
#pragma unroll 1
    for (int i = 0; i < K_; i++) {
        unsigned long long mykey = key[0];
        unsigned long long m = mykey;
#pragma unroll
        for (int off = 16; off; off >>= 1) {
            unsigned long long o = __shfl_down_sync(0xffffffffu, m, off);
            m = (o < m) ? o : m;
        }
        m = __shfl_sync(0xffffffffu, m, 0);
        if (lane == 0) cand[wid][i] = m;
        if (mykey == m) {   // keys unique (index embedded) -> exactly one lane
            key[0] = key[1]; key[1] = key[2]; key[2] = key[3];
            key[3] = ~0ULL;
        }
    }
    __syncthreads();

    // 8-way merge of sorted candidate lists, done by warp 0 (lanes 0..7 own lists)
    if (wid == 0) {
        int q = 0;
        const int out_base = row * K_;
#pragma unroll 1
        for (int i = 0; i < K_; i++) {
            unsigned long long mykey = (lane < 8) ? cand[lane][q] : ~0ULL;
            unsigned long long m = mykey;
#pragma unroll
            for (int off = 4; off; off >>= 1) {
                unsigned long long o = __shfl_down_sync(0xffffffffu, m, off);
                m = (o < m) ? o : m;
            }
            m = __shfl_sync(0xffffffffu, m, 0);
            if (lane == 0) g_nn_idx[out_base + i] = (int)(unsigned)(m & 0xFFFFFFFFu);
            if (mykey == m && lane < 8) q++;
        }
    }
}

// ---------------------------------------------------------------------------
// Kernel 2: fused gather + (edge@w1+BN+relu) + (@w2+BN+relu) + mean over k.
// BN folded into weights. edge@w1 split: center part computed once per node,
// diff part per neighbor. Thread c owns output channel c; weight columns live
// in registers; activations broadcast from smem (conflict-free LDS.128).
// ALL K=20 neighbors are processed per barrier interval: 2 syncs per node.
// 128 threads = 2 groups of 64; each block handles 16 nodes (8 per group).
// ---------------------------------------------------------------------------
#define ITERS_ 8

__global__ void __launch_bounds__(128, 2) edgeconv_kernel(
    const float* __restrict__ feats,
    const float* __restrict__ w1,  const float* __restrict__ b1,
    const float* __restrict__ g1,  const float* __restrict__ be1,
    const float* __restrict__ mu1, const float* __restrict__ v1,
    const float* __restrict__ w2,  const float* __restrict__ b2,
    const float* __restrict__ g2,  const float* __restrict__ be2,
    const float* __restrict__ mu2, const float* __restrict__ v2,
    float* __restrict__ out)
{
    __shared__ __align__(16) float w1c_s[D_ * C_];      // folded w1[0:64,:], [d][c]
    __shared__ __align__(16) float cf[2][C_];
    __shared__ __align__(16) float dbuf[2][K_][C_];     // all K diff vectors
    __shared__ __align__(16) float hbuf[2][K_][C_];     // all K hidden vectors

    const int tid = threadIdx.x;
    const int c   = tid & (C_ - 1);
    const int grp = tid >> 6;

    const float s1c = g1[c] * rsqrtf(v1[c] + EPS_);
    const float b1f = (b1[c] - mu1[c]) * s1c + be1[c];
    const float s2c = g2[c] * rsqrtf(v2[c] + EPS_);
    const float b2f = (b2[c] - mu2[c]) * s2c + be2[c];

    float w1d_col[D_];   // folded w1[64+d][c]
    float w2_col[C_];    // folded w2[e][c]
#pragma unroll
    for (int d = 0; d < D_; d++) w1d_col[d] = w1[(D_ + d) * C_ + c] * s1c;
#pragma unroll
    for (int e = 0; e < C_; e++) w2_col[e]  = w2[e * C_ + c] * s2c;
    if (grp == 0) {
#pragma unroll
        for (int d = 0; d < D_; d++) w1c_s[d * C_ + c] = w1[d * C_ + c] * s1c;
    }
    __syncthreads();

#pragma unroll 1
    for (int i = 0; i < ITERS_; i++) {
        const int node  = blockIdx.x * (2 * ITERS_) + i * 2 + grp;   // b*N + n
        const int bbase = (node >> 10) << 10;                        // b*N
        const float fc  = feats[node * D_ + c];
        cf[grp][c] = fc;

        // gather all K neighbor diffs (coalesced 256B rows, high MLP)
        const int* nn = g_nn_idx + node * K_;
#pragma unroll
        for (int k = 0; k < K_; k++) {
            dbuf[grp][k][c] = feats[(bbase + nn[k]) * D_ + c] - fc;
        }
        __syncthreads();

        // center contribution to layer-1 pre-activation (once per node)
        float cp0 = b1f, cp1 = 0.f, cp2 = 0.f, cp3 = 0.f;
#pragma unroll
        for (int d = 0; d < D_; d += 4) {
            float4 dv = *(const float4*)&cf[grp][d];
            cp0 += dv.x * w1c_s[(d + 0) * C_ + c];
            cp1 += dv.y * w1c_s[(d + 1) * C_ + c];
            cp2 += dv.z * w1c_s[(d + 2) * C_ + c];
            cp3 += dv.w * w1c_s[(d + 3) * C_ + c];
        }
        const float cpart = (cp0 + cp1) + (cp2 + cp3);

        // layer 1: all K, tiled 4 wide for ILP (4 independent FMA chains)
#pragma unroll 1
        for (int t = 0; t < K_; t += 4) {
            float h0 = cpart, h1 = cpart, h2 = cpart, h3 = cpart;
#pragma unroll
            for (int d = 0; d < D_; d += 4) {
                float4 v0 = *(const float4*)&dbuf[grp][t + 0][d];
                float4 v1_ = *(const float4*)&dbuf[grp][t + 1][d];
                float4 v2_ = *(const float4*)&dbuf[grp][t + 2][d];
                float4 v3 = *(const float4*)&dbuf[grp][t + 3][d];
                h0 += v0.x * w1d_col[d]     + v0.y * w1d_col[d + 1]
                    + v0.z * w1d_col[d + 2] + v0.w * w1d_col[d + 3];
                h1 += v1_.x * w1d_col[d]     + v1_.y * w1d_col[d + 1]
                    + v1_.z * w1d_col[d + 2] + v1_.w * w1d_col[d + 3];
                h2 += v2_.x * w1d_col[d]     + v2_.y * w1d_col[d + 1]
                    + v2_.z * w1d_col[d + 2] + v2_.w * w1d_col[d + 3];
                h3 += v3.x * w1d_col[d]     + v3.y * w1d_col[d + 1]
                    + v3.z * w1d_col[d + 2] + v3.w * w1d_col[d + 3];
            }
            hbuf[grp][t + 0][c] = fmaxf(h0, 0.f);
            hbuf[grp][t + 1][c] = fmaxf(h1, 0.f);
            hbuf[grp][t + 2][c] = fmaxf(h2, 0.f);
            hbuf[grp][t + 3][c] = fmaxf(h3, 0.f);
        }
        __syncthreads();

        // layer 2: all K, tiled 4 wide; accumulate mean
        float acc = 0.f;
#pragma unroll 1
        for (int t = 0; t < K_; t += 4) {
            float y0 = b2f, y1 = b2f, y2 = b2f, y3 = b2f;
#pragma unroll
            for (int e = 0; e < C_; e += 4) {
                float4 v0 = *(const float4*)&hbuf[grp][t + 0][e];
                float4 v1_ = *(const float4*)&hbuf[grp][t + 1][e];
                float4 v2_ = *(const float4*)&hbuf[grp][t + 2][e];
                float4 v3 = *(const float4*)&hbuf[grp][t + 3][e];
                y0 += v0.x * w2_col[e]     + v0.y * w2_col[e + 1]
                    + v0.z * w2_col[e + 2] + v0.w * w2_col[e + 3];
                y1 += v1_.x * w2_col[e]     + v1_.y * w2_col[e + 1]
                    + v1_.z * w2_col[e + 2] + v1_.w * w2_col[e + 3];
                y2 += v2_.x * w2_col[e]     + v2_.y * w2_col[e + 1]
                    + v2_.z * w2_col[e + 2] + v2_.w * w2_col[e + 3];
                y3 += v3.x * w2_col[e]     + v3.y * w2_col[e + 1]
                    + v3.z * w2_col[e + 2] + v3.w * w2_col[e + 3];
            }
            acc += fmaxf(y0, 0.f) + fmaxf(y1, 0.f) + fmaxf(y2, 0.f) + fmaxf(y3, 0.f);
        }
        out[node * C_ + c] = acc * (1.0f / K_);
        // next iteration's cf/dbuf writes conflict only with reads that ended
        // before the mid-node sync; hbuf writes happen after next node's first
        // sync, which orders them against this node's hbuf reads.
    }
}

// ---------------------------------------------------------------------------
extern "C" void kernel_launch(void* const* d_in, const int* in_sizes, int n_in,
                              void* d_out, int out_size)
{
    const float* feats = (const float*)d_in[0];
    const float* adj   = (const float*)d_in[1];
    const float* w1    = (const float*)d_in[2];
    const float* b1    = (const float*)d_in[3];
    const float* g1    = (const float*)d_in[4];
    const float* be1   = (const float*)d_in[5];
    const float* mu1   = (const float*)d_in[6];
    const float* v1    = (const float*)d_in[7];
    const float* w2    = (const float*)d_in[8];
    const float* b2    = (const float*)d_in[9];
    const float* g2    = (const float*)d_in[10];
    const float* be2   = (const float*)d_in[11];
    const float* mu2   = (const float*)d_in[12];
    const float* v2    = (const float*)d_in[13];
    float* out = (float*)d_out;

    extract_f0_kernel<<<(B_ * N_ + 1023) / 1024, 1024>>>(feats);
    topk_kernel<<<B_ * N_, 256>>>(adj);
    edgeconv_kernel<<<(B_ * N_) / 16, 128>>>(feats, w1, b1, g1, be1, mu1, v1,
                                             w2, b2, g2, be2, mu2, v2, out);
}

// round 3
// speedup vs baseline: 1.8910x; 1.4604x over previous
#include <cuda_runtime.h>

#define B_ 16
#define N_ 1024
#define D_ 64
#define C_ 64
#define K_ 20
#define EPS_ 0.001f
#define ITERS_ 8

// scratch (no cudaMalloc allowed)
__device__ int   g_nn_idx[B_ * N_ * K_];
__device__ float g_f0[B_ * N_];

// ---------------------------------------------------------------------------
// packed fp32x2 helpers (sm_103a FFMA2)
// ---------------------------------------------------------------------------
__device__ __forceinline__ unsigned long long pack2(float x, float y) {
    float2 f = make_float2(x, y);
    return *reinterpret_cast<unsigned long long*>(&f);
}
__device__ __forceinline__ float2 unpack2(unsigned long long u) {
    return *reinterpret_cast<float2*>(&u);
}
__device__ __forceinline__ unsigned long long ffma2(unsigned long long a,
                                                    unsigned long long b,
                                                    unsigned long long c) {
    unsigned long long d;
    asm("fma.rn.f32x2 %0, %1, %2, %3;" : "=l"(d) : "l"(a), "l"(b), "l"(c));
    return d;
}

// ---------------------------------------------------------------------------
// Kernel 0: densify f0 = feats[:,:,0]
// ---------------------------------------------------------------------------
__global__ void extract_f0_kernel(const float* __restrict__ feats) {
    int i = blockIdx.x * blockDim.x + threadIdx.x;
    if (i < B_ * N_) g_f0[i] = feats[(size_t)i * D_];
}

// ---------------------------------------------------------------------------
// Kernel 1: exact top-20 smallest of a[j] = adj[b,n,j]*|f0[b,j]-f0[b,n]|.
// Per-thread sorted-4 lists (key = valbits<<32 | j, unique), then 20x
// warp argmin via two u32 REDUX.MIN (value, then index among value-ties),
// then 8-list merge on warp 0 the same way.
// ---------------------------------------------------------------------------
__global__ void topk_kernel(const float* __restrict__ adj) {
    const int row  = blockIdx.x;            // b*N + n
    const int b    = row >> 10;
    const int tid  = threadIdx.x;           // 256 threads
    const int lane = tid & 31;
    const int wid  = tid >> 5;              // 8 warps

    const float  f0n  = g_f0[row];
    const float* arow = adj + (size_t)row * N_;
    const float* f0b  = g_f0 + b * N_;

    unsigned long long key[4];
#pragma unroll
    for (int t = 0; t < 4; t++) {
        int j = tid + t * 256;
        float a = arow[j] * fabsf(f0b[j] - f0n);
        key[t] = ((unsigned long long)__float_as_uint(a) << 32) | (unsigned)j;
    }
#define CSWP(x, y) { unsigned long long lo = (x) < (y) ? (x) : (y); \
                     unsigned long long hi = (x) < (y) ? (y) : (x); (x) = lo; (y) = hi; }
    CSWP(key[0], key[1]); CSWP(key[2], key[3]);
    CSWP(key[0], key[2]); CSWP(key[1], key[3]);
    CSWP(key[1], key[2]);
#undef CSWP

    __shared__ unsigned long long cand[8][K_];

    // per-warp top-20 of its 128 elements
#pragma unroll 1
    for (int i = 0; i < K_; i++) {
        unsigned v = (unsigned)(key[0] >> 32);
        unsigned m = __reduce_min_sync(0xffffffffu, v);
        unsigned ic = (v == m) ? (unsigned)key[0] : 0xffffffffu;
        unsigned mi = __reduce_min_sync(0xffffffffu, ic);
        if (lane == 0) cand[wid][i] = ((unsigned long long)m << 32) | mi;
        if (v == m && (unsigned)key[0] == mi) {
            key[0] = key[1]; key[1] = key[2]; key[2] = key[3];
            key[3] = ~0ULL;
        }
    }
    __syncthreads();

    // merge 8 sorted lists on warp 0
    if (wid == 0) {
        int q = 0;
        const int out_base = row * K_;
#pragma unroll 1
        for (int i = 0; i < K_; i++) {
            unsigned long long myk = (lane < 8) ? cand[lane][q] : ~0ULL;
            unsigned v = (unsigned)(myk >> 32);
            unsigned m = __reduce_min_sync(0xffffffffu, v);
            unsigned ic = (v == m) ? (unsigned)myk : 0xffffffffu;
            unsigned mi = __reduce_min_sync(0xffffffffu, ic);
            if (lane == 0) g_nn_idx[out_base + i] = (int)mi;
            if (v == m && (unsigned)myk == mi) q++;
        }
    }
}

// ---------------------------------------------------------------------------
// Kernel 2: fused gather + MLP + mean, FFMA2 along the reduction dim.
// Thread c owns output channel c. Packed weight pairs {w_d, w_{d+1}} live in
// registers; activation pairs come directly from broadcast LDS.128 halves.
// Next node's gather is software-pipelined (LDG early, STS after layer-1).
// 128 threads = 2 groups of 64; block handles 16 nodes.
// ---------------------------------------------------------------------------
__global__ void __launch_bounds__(128, 2) edgeconv_kernel(
    const float* __restrict__ feats,
    const float* __restrict__ w1,  const float* __restrict__ b1,
    const float* __restrict__ g1,  const float* __restrict__ be1,
    const float* __restrict__ mu1, const float* __restrict__ v1,
    const float* __restrict__ w2,  const float* __restrict__ b2,
    const float* __restrict__ g2,  const float* __restrict__ be2,
    const float* __restrict__ mu2, const float* __restrict__ v2,
    float* __restrict__ out)
{
    __shared__ __align__(16) float w1c_s[D_ * C_];        // folded w1[0:64,:], [d][c]
    __shared__ __align__(16) float cf[2][2][C_];          // [grp][buf]
    __shared__ __align__(16) float dbuf[2][2][K_][C_];    // [grp][buf][k][d]
    __shared__ __align__(16) float hbuf[2][K_][C_];       // [grp][k][e]

    const int tid = threadIdx.x;
    const int c   = tid & (C_ - 1);
    const int grp = tid >> 6;
    const int bbase = ((blockIdx.x * (2 * ITERS_)) >> 10) << 10;   // b*N (const per block)

    const float s1c = g1[c] * rsqrtf(v1[c] + EPS_);
    const float b1f = (b1[c] - mu1[c]) * s1c + be1[c];
    const float s2c = g2[c] * rsqrtf(v2[c] + EPS_);
    const float b2f = (b2[c] - mu2[c]) * s2c + be2[c];

    unsigned long long W1[D_ / 2];   // packed folded w1[64+2i .. 64+2i+1][c]
    unsigned long long W2[C_ / 2];   // packed folded w2[2i .. 2i+1][c]
#pragma unroll
    for (int i = 0; i < D_ / 2; i++)
        W1[i] = pack2(w1[(D_ + 2 * i) * C_ + c] * s1c,
                      w1[(D_ + 2 * i + 1) * C_ + c] * s1c);
#pragma unroll
    for (int i = 0; i < C_ / 2; i++)
        W2[i] = pack2(w2[(2 * i) * C_ + c] * s2c,
                      w2[(2 * i + 1) * C_ + c] * s2c);
    if (grp == 0) {
#pragma unroll
        for (int d = 0; d < D_; d++) w1c_s[d * C_ + c] = w1[d * C_ + c] * s1c;
    }

    // gather node i=0 for this group (direct path)
    {
        const int node0 = blockIdx.x * (2 * ITERS_) + grp;
        const float fc0 = feats[node0 * D_ + c];
        cf[grp][0][c] = fc0;
        const int* nn = g_nn_idx + node0 * K_;
#pragma unroll
        for (int k = 0; k < K_; k++)
            dbuf[grp][0][k][c] = feats[(bbase + nn[k]) * D_ + c] - fc0;
    }

#pragma unroll 1
    for (int i = 0; i < ITERS_; i++) {
        const int cur  = i & 1, nxt = cur ^ 1;
        const int node = blockIdx.x * (2 * ITERS_) + i * 2 + grp;
        __syncthreads();   // dbuf[cur]/cf[cur] ready; prev layer-2 hbuf reads done

        // ---- prefetch node i+1 into registers (stores deferred past layer-1)
        float pre[K_];
        float fcn = 0.f;
        if (i < ITERS_ - 1) {
            const int node2 = node + 2;
            const int* nn2  = g_nn_idx + node2 * K_;
            fcn = feats[node2 * D_ + c];
#pragma unroll
            for (int k = 0; k < K_; k++)
                pre[k] = feats[(bbase + nn2[k]) * D_ + c];
        }

        // ---- center contribution (scalar, small)
        float cp0 = b1f, cp1 = 0.f, cp2 = 0.f, cp3 = 0.f;
#pragma unroll
        for (int d = 0; d < D_; d += 4) {
            float4 dv = *(const float4*)&cf[grp][cur][d];
            cp0 += dv.x * w1c_s[(d + 0) * C_ + c];
            cp1 += dv.y * w1c_s[(d + 1) * C_ + c];
            cp2 += dv.z * w1c_s[(d + 2) * C_ + c];
            cp3 += dv.w * w1c_s[(d + 3) * C_ + c];
        }
        const unsigned long long pc = pack2((cp0 + cp1) + (cp2 + cp3), 0.f);

        // ---- layer 1: all K, packed along d, k-tiled 4
#pragma unroll 1
        for (int t = 0; t < K_; t += 4) {
            unsigned long long A0 = pc, A1 = pc, A2 = pc, A3 = pc;
#pragma unroll
            for (int d = 0; d < D_; d += 4) {
                const int w = d >> 1;
                ulonglong2 q0 = *(const ulonglong2*)&dbuf[grp][cur][t + 0][d];
                ulonglong2 q1 = *(const ulonglong2*)&dbuf[grp][cur][t + 1][d];
                ulonglong2 q2 = *(const ulonglong2*)&dbuf[grp][cur][t + 2][d];
                ulonglong2 q3 = *(const ulonglong2*)&dbuf[grp][cur][t + 3][d];
                A0 = ffma2(q0.x, W1[w], A0);  A0 = ffma2(q0.y, W1[w + 1], A0);
                A1 = ffma2(q1.x, W1[w], A1);  A1 = ffma2(q1.y, W1[w + 1], A1);
                A2 = ffma2(q2.x, W1[w], A2);  A2 = ffma2(q2.y, W1[w + 1], A2);
                A3 = ffma2(q3.x, W1[w], A3);  A3 = ffma2(q3.y, W1[w + 1], A3);
            }
            float2 a0 = unpack2(A0), a1 = unpack2(A1), a2 = unpack2(A2), a3 = unpack2(A3);
            hbuf[grp][t + 0][c] = fmaxf(a0.x + a0.y, 0.f);
            hbuf[grp][t + 1][c] = fmaxf(a1.x + a1.y, 0.f);
            hbuf[grp][t + 2][c] = fmaxf(a2.x + a2.y, 0.f);
            hbuf[grp][t + 3][c] = fmaxf(a3.x + a3.y, 0.f);
        }

        // ---- store prefetched gather (LDG data has long arrived)
        if (i < ITERS_ - 1) {
            cf[grp][nxt][c] = fcn;
#pragma unroll
            for (int k = 0; k < K_; k++)
                dbuf[grp][nxt][k][c] = pre[k] - fcn;
        }
        __syncthreads();   // hbuf ready; dbuf[nxt] ready

        // ---- layer 2: all K, packed along e, k-tiled 4; mean accumulate
        const unsigned long long pb = pack2(b2f, 0.f);
        float acc = 0.f;
#pragma unroll 1
        for (int t = 0; t < K_; t += 4) {
            unsigned long long A0 = pb, A1 = pb, A2 = pb, A3 = pb;
#pragma unroll
            for (int e = 0; e < C_; e += 4) {
                const int w = e >> 1;
                ulonglong2 q0 = *(const ulonglong2*)&hbuf[grp][t + 0][e];
                ulonglong2 q1 = *(const ulonglong2*)&hbuf[grp][t + 1][e];
                ulonglong2 q2 = *(const ulonglong2*)&hbuf[grp][t + 2][e];
                ulonglong2 q3 = *(const ulonglong2*)&hbuf[grp][t + 3][e];
                A0 = ffma2(q0.x, W2[w], A0);  A0 = ffma2(q0.y, W2[w + 1], A0);
                A1 = ffma2(q1.x, W2[w], A1);  A1 = ffma2(q1.y, W2[w + 1], A1);
                A2 = ffma2(q2.x, W2[w], A2);  A2 = ffma2(q2.y, W2[w + 1], A2);
                A3 = ffma2(q3.x, W2[w], A3);  A3 = ffma2(q3.y, W2[w + 1], A3);
            }
            float2 a0 = unpack2(A0), a1 = unpack2(A1), a2 = unpack2(A2), a3 = unpack2(A3);
            acc += fmaxf(a0.x + a0.y, 0.f) + fmaxf(a1.x + a1.y, 0.f)
                 + fmaxf(a2.x + a2.y, 0.f) + fmaxf(a3.x + a3.y, 0.f);
        }
        out[node * C_ + c] = acc * (1.0f / K_);
    }
}

// ---------------------------------------------------------------------------
extern "C" void kernel_launch(void* const* d_in, const int* in_sizes, int n_in,
                              void* d_out, int out_size)
{
    const float* feats = (const float*)d_in[0];
    const float* adj   = (const float*)d_in[1];
    const float* w1    = (const float*)d_in[2];
    const float* b1    = (const float*)d_in[3];
    const float* g1    = (const float*)d_in[4];
    const float* be1   = (const float*)d_in[5];
    const float* mu1   = (const float*)d_in[6];
    const float* v1    = (const float*)d_in[7];
    const float* w2    = (const float*)d_in[8];
    const float* b2    = (const float*)d_in[9];
    const float* g2    = (const float*)d_in[10];
    const float* be2   = (const float*)d_in[11];
    const float* mu2   = (const float*)d_in[12];
    const float* v2    = (const float*)d_in[13];
    float* out = (float*)d_out;

    extract_f0_kernel<<<(B_ * N_ + 1023) / 1024, 1024>>>(feats);
    topk_kernel<<<B_ * N_, 256>>>(adj);
    edgeconv_kernel<<<(B_ * N_) / 16, 128>>>(feats, w1, b1, g1, be1, mu1, v1,
                                             w2, b2, g2, be2, mu2, v2, out);
}